// round 16
// baseline (speedup 1.0000x reference)
#include <cuda_runtime.h>
#include <cuda_bf16.h>
#include <cstdint>

// Problem dims (fixed by the dataset)
#define BB 256
#define TT 256
#define DD 128
#define HH 256
#define NROWS (BB*TT)          // 65536

// Scratch: h1 (post-LN, pre-LIF1) [B,T,H]; pre-split swizzled W planes
__device__ __align__(16) float g_h1[(size_t)NROWS * HH];   // 67 MB
__device__ __align__(16) unsigned char g_w1p[3*65536];     // W1 bf16x3 planes
__device__ __align__(16) unsigned char g_w2p[3*65536];     // W2 bf16x3 planes

// ---------------------------------------------------------------------------
// mma.sync / ldmatrix helpers (family-portable; NO tcgen05 — harness PTX
// target is plain sm_103, arch-specific features are rejected by ptxas)
// ---------------------------------------------------------------------------
__device__ __forceinline__ uint32_t smem_to_u32(const void* p) {
    uint32_t a;
    asm("{ .reg .u64 t; cvta.to.shared.u64 t, %1; cvt.u32.u64 %0, t; }"
        : "=r"(a) : "l"(p));
    return a;
}
#define LDSM4(r, addr) \
    asm volatile("ldmatrix.sync.aligned.m8n8.x4.shared.b16 {%0,%1,%2,%3}, [%4];" \
        : "=r"((r)[0]), "=r"((r)[1]), "=r"((r)[2]), "=r"((r)[3]) : "r"(addr))
#define MMA16816(D, a, b0, b1) \
    asm volatile("mma.sync.aligned.m16n8k16.row.col.f32.bf16.bf16.f32 " \
        "{%0,%1,%2,%3}, {%4,%5,%6,%7}, {%8,%9}, {%0,%1,%2,%3};" \
        : "+f"((D)[0]), "+f"((D)[1]), "+f"((D)[2]), "+f"((D)[3]) \
        : "r"((a)[0]), "r"((a)[1]), "r"((a)[2]), "r"((a)[3]), "r"(b0), "r"(b1))
// named barriers: group-scope sync (ids 1-7; 0 is __syncthreads)
#define BARN(id, cnt) asm volatile("bar.sync %0, %1;" :: "r"(id), "r"(cnt) : "memory")

__device__ __forceinline__ uint32_t packbf(__nv_bfloat16 a, __nv_bfloat16 b) {
    return (uint32_t)__bfloat16_as_ushort(a) | ((uint32_t)__bfloat16_as_ushort(b) << 16);
}
// scalar split (prep kernel only): f = h + m + l
__device__ __forceinline__ void split3(float2 f, uint32_t& h, uint32_t& m, uint32_t& l) {
    __nv_bfloat16 hx = __float2bfloat16(f.x); float rx = f.x - __bfloat162float(hx);
    __nv_bfloat16 mx = __float2bfloat16(rx);  rx -= __bfloat162float(mx);
    __nv_bfloat16 lx = __float2bfloat16(rx);
    __nv_bfloat16 hy = __float2bfloat16(f.y); float ry = f.y - __bfloat162float(hy);
    __nv_bfloat16 my = __float2bfloat16(ry);  ry -= __bfloat162float(my);
    __nv_bfloat16 ly = __float2bfloat16(ry);
    h = packbf(hx, hy); m = packbf(mx, my); l = packbf(lx, ly);
}
// packed split (hot path): bf16x2 cvt + shift/mask upconvert; bit-identical
__device__ __forceinline__ void split3p(float2 f, uint32_t& h, uint32_t& m, uint32_t& l) {
    asm("cvt.rn.bf16x2.f32 %0, %1, %2;" : "=r"(h) : "f"(f.y), "f"(f.x));
    float rx = f.x - __uint_as_float(h << 16);
    float ry = f.y - __uint_as_float(h & 0xFFFF0000u);
    asm("cvt.rn.bf16x2.f32 %0, %1, %2;" : "=r"(m) : "f"(ry), "f"(rx));
    float sx = rx - __uint_as_float(m << 16);
    float sy = ry - __uint_as_float(m & 0xFFFF0000u);
    asm("cvt.rn.bf16x2.f32 %0, %1, %2;" : "=r"(l) : "f"(sy), "f"(sx));
}

// ---------------------------------------------------------------------------
// Prep kernel: split W1/W2 into swizzled bf16 planes ONCE
// ---------------------------------------------------------------------------
__global__ __launch_bounds__(512)
void prep_kernel(const float* __restrict__ W1, const float* __restrict__ W2)
{
    int idx = blockIdx.x * 512 + threadIdx.x;     // 0..32767
    if (idx < 16384) {                            // W1: [h=256][k=128]
        int h = idx >> 6, k = (idx & 63) * 2;
        float2 w = *(const float2*)(W1 + h*128 + k);
        uint32_t ph, pm, pl;
        split3(w, ph, pm, pl);
        uint32_t off = (uint32_t)h*256 + ((((uint32_t)k >> 3) ^ (h & 7)) << 4)
                     + ((k & 7) << 1);
        *(uint32_t*)(g_w1p + off)           = ph;
        *(uint32_t*)(g_w1p + 65536 + off)   = pm;
        *(uint32_t*)(g_w1p + 2*65536 + off) = pl;
    } else {                                      // W2: [d=128][k=256]
        int j = idx - 16384;
        int dd = j >> 7, k = (j & 127) * 2;
        float2 w = *(const float2*)(W2 + dd*256 + k);
        uint32_t ph, pm, pl;
        split3(w, ph, pm, pl);
        uint32_t off = (uint32_t)dd*512 + ((((uint32_t)k >> 3) ^ (dd & 7)) << 4)
                     + ((k & 7) << 1);
        *(uint32_t*)(g_w2p + off)           = ph;
        *(uint32_t*)(g_w2p + 65536 + off)   = pm;
        *(uint32_t*)(g_w2p + 2*65536 + off) = pl;
    }
}

// ---------------------------------------------------------------------------
// Kernel 1: GEMM1 (HMMA bf16x3, register A-fragments) + bias + LN -> g_h1
// Grid 512 (one 128-row tile per block) -> uses all 148 SMs, 3.46 waves.
// smem: params 0..3071 | red 3072..7168 | W1 planes 8192..204800
// ---------------------------------------------------------------------------
#define OFF_RED  3072
#define OFF_W    8192
#define W1P      65536
#define G1_SMEM  (OFF_W + 3*W1P)           // 204800

__global__ __launch_bounds__(512, 1)
void gemm1_kernel(const float* __restrict__ x,
                  const float* __restrict__ b1,
                  const float* __restrict__ g1,
                  const float* __restrict__ be1)
{
    extern __shared__ __align__(16) char smem[];
    const int tid  = threadIdx.x;
    const int lane = tid & 31;
    const int wid  = tid >> 5;

    float* b1s  = (float*)smem;
    float* g1s  = b1s + 256;
    float* be1s = g1s + 256;
    float* red  = (float*)(smem + OFF_RED);   // [128 rows][8] per-group disjoint
    char*  wsm  = smem + OFF_W;

    if (tid < 256) { b1s[tid] = b1[tid]; g1s[tid] = g1[tid]; be1s[tid] = be1[tid]; }

    const int wm = wid >> 2, wn = wid & 3;
    const int gbar = 4 + wm;
    const int brow = wn*64 + (lane & 7) + ((lane >> 4) << 3);
    const int bsel = (lane >> 3) & 1;
    const uint32_t wsm_u = smem_to_u32(wsm);
    const int rowBase = blockIdx.x * 128;
    const float* xg = x + (size_t)(rowBase + wm*32) * DD;

    // prefetch ks=0 A-fragments (issues before/while W1 staging)
    float2 pf[2][4];
    #pragma unroll
    for (int mt = 0; mt < 2; mt++) {
        const float* xr = xg + (mt*16 + (lane >> 2))*DD + (lane & 3)*2;
        pf[mt][0] = *(const float2*)(xr);
        pf[mt][1] = *(const float2*)(xr + 8*DD);
        pf[mt][2] = *(const float2*)(xr + 8);
        pf[mt][3] = *(const float2*)(xr + 8*DD + 8);
    }

    // Stage W1 planes: straight copy (prep kernel already split+swizzled)
    {
        const uint4* src = (const uint4*)g_w1p;   // 12288 uint4
        uint4* dst = (uint4*)wsm;
        #pragma unroll 6
        for (int i = 0; i < 24; i++) dst[tid + i*512] = src[tid + i*512];
    }
    __syncthreads();

    float d[2][8][4];
    #pragma unroll
    for (int mt = 0; mt < 2; mt++)
        #pragma unroll
        for (int nt = 0; nt < 8; nt++)
            #pragma unroll
            for (int i = 0; i < 4; i++) d[mt][nt][i] = 0.f;

    for (int ks = 0; ks < 8; ks++) {
        // build A fragments in registers (bit-identical planes)
        uint32_t ah[2][4], am[2][4], al[2][4];
        #pragma unroll
        for (int mt = 0; mt < 2; mt++)
            #pragma unroll
            for (int i = 0; i < 4; i++)
                split3p(pf[mt][i], ah[mt][i], am[mt][i], al[mt][i]);

        // prefetch ks+1 (hidden behind MMA burst)
        if (ks < 7) {
            #pragma unroll
            for (int mt = 0; mt < 2; mt++) {
                const float* xr = xg + (mt*16 + (lane >> 2))*DD
                                + (ks+1)*16 + (lane & 3)*2;
                pf[mt][0] = *(const float2*)(xr);
                pf[mt][1] = *(const float2*)(xr + 8*DD);
                pf[mt][2] = *(const float2*)(xr + 8);
                pf[mt][3] = *(const float2*)(xr + 8*DD + 8);
            }
        }

        #pragma unroll
        for (int np = 0; np < 4; np++) {
            int row = brow + np*16;
            uint32_t boff = (uint32_t)row*256 +
                            ((((ks << 1) | bsel) ^ (row & 7)) << 4);
            uint32_t bh[4], bm[4], bl[4];
            LDSM4(bh, wsm_u + boff);
            LDSM4(bm, wsm_u + W1P + boff);
            LDSM4(bl, wsm_u + 2*W1P + boff);
            // term-outer ordering: accumulator RAW chains spaced by 3
            // independent MMAs; per-accumulator order unchanged (hh,hm,mh,
            // mm,hl,lh) -> bit-identical accumulation
            #pragma unroll
            for (int mt = 0; mt < 2; mt++)
                #pragma unroll
                for (int ns = 0; ns < 2; ns++)
                    MMA16816(d[mt][np*2 + ns], ah[mt], bh[ns*2], bh[ns*2+1]);
            #pragma unroll
            for (int mt = 0; mt < 2; mt++)
                #pragma unroll
                for (int ns = 0; ns < 2; ns++)
                    MMA16816(d[mt][np*2 + ns], ah[mt], bm[ns*2], bm[ns*2+1]);
            #pragma unroll
            for (int mt = 0; mt < 2; mt++)
                #pragma unroll
                for (int ns = 0; ns < 2; ns++)
                    MMA16816(d[mt][np*2 + ns], am[mt], bh[ns*2], bh[ns*2+1]);
            #pragma unroll
            for (int mt = 0; mt < 2; mt++)
                #pragma unroll
                for (int ns = 0; ns < 2; ns++)
                    MMA16816(d[mt][np*2 + ns], am[mt], bm[ns*2], bm[ns*2+1]);
            #pragma unroll
            for (int mt = 0; mt < 2; mt++)
                #pragma unroll
                for (int ns = 0; ns < 2; ns++)
                    MMA16816(d[mt][np*2 + ns], ah[mt], bl[ns*2], bl[ns*2+1]);
            #pragma unroll
            for (int mt = 0; mt < 2; mt++)
                #pragma unroll
                for (int ns = 0; ns < 2; ns++)
                    MMA16816(d[mt][np*2 + ns], al[mt], bh[ns*2], bh[ns*2+1]);
        }
    }

    // ---- epilogue (group-local): bias + LN + store ----
    float psum[2][2] = {{0.f,0.f},{0.f,0.f}}, psq[2][2] = {{0.f,0.f},{0.f,0.f}};
    #pragma unroll
    for (int mt = 0; mt < 2; mt++)
        #pragma unroll
        for (int nt = 0; nt < 8; nt++) {
            int col = wn*64 + nt*8 + (lane & 3)*2;
            float bx = b1s[col], by = b1s[col+1];
            float* D = d[mt][nt];
            D[0] += bx; D[1] += by; D[2] += bx; D[3] += by;
            psum[mt][0] += D[0] + D[1]; psq[mt][0] += D[0]*D[0] + D[1]*D[1];
            psum[mt][1] += D[2] + D[3]; psq[mt][1] += D[2]*D[2] + D[3]*D[3];
        }
    #pragma unroll
    for (int mt = 0; mt < 2; mt++)
        #pragma unroll
        for (int rh = 0; rh < 2; rh++) {
            #pragma unroll
            for (int o = 1; o <= 2; o <<= 1) {
                psum[mt][rh] += __shfl_xor_sync(0xffffffffu, psum[mt][rh], o);
                psq[mt][rh]  += __shfl_xor_sync(0xffffffffu, psq[mt][rh],  o);
            }
            if ((lane & 3) == 0) {
                int r = wm*32 + mt*16 + rh*8 + (lane >> 2);
                red[r*8 + wn*2 + 0] = psum[mt][rh];
                red[r*8 + wn*2 + 1] = psq[mt][rh];
            }
        }
    BARN(gbar, 128);   // red rows for this group complete

    #pragma unroll
    for (int mt = 0; mt < 2; mt++) {
        int r0 = wm*32 + mt*16 + (lane >> 2);
        int r1 = r0 + 8;
        float s0 = red[r0*8+0] + red[r0*8+2] + red[r0*8+4] + red[r0*8+6];
        float q0 = red[r0*8+1] + red[r0*8+3] + red[r0*8+5] + red[r0*8+7];
        float mean0 = s0 * (1.f/256.f);
        float var0  = fmaxf(q0 * (1.f/256.f) - mean0*mean0, 0.f) + 1e-5f;
        float inv0  = rsqrtf(var0);
        inv0 = inv0 * (1.5f - 0.5f * var0 * inv0 * inv0);  // fp32-exact rsqrt
        float s1 = red[r1*8+0] + red[r1*8+2] + red[r1*8+4] + red[r1*8+6];
        float q1 = red[r1*8+1] + red[r1*8+3] + red[r1*8+5] + red[r1*8+7];
        float mean1 = s1 * (1.f/256.f);
        float var1  = fmaxf(q1 * (1.f/256.f) - mean1*mean1, 0.f) + 1e-5f;
        float inv1  = rsqrtf(var1);
        inv1 = inv1 * (1.5f - 0.5f * var1 * inv1 * inv1);
        float* o0 = g_h1 + (size_t)(rowBase + r0) * HH;
        float* o1 = o0 + 8*HH;
        #pragma unroll
        for (int nt = 0; nt < 8; nt++) {
            int col = wn*64 + nt*8 + (lane & 3)*2;
            float gx = g1s[col], gy = g1s[col+1];
            float ex = be1s[col], ey = be1s[col+1];
            float* D = d[mt][nt];
            float2 w0, w1;
            w0.x = (D[0] - mean0) * inv0 * gx + ex;
            w0.y = (D[1] - mean0) * inv0 * gy + ey;
            w1.x = (D[2] - mean1) * inv1 * gx + ex;
            w1.y = (D[3] - mean1) * inv1 * gy + ey;
            *(float2*)(o0 + col) = w0;
            *(float2*)(o1 + col) = w1;
        }
    }
}

// ---------------------------------------------------------------------------
// Kernel 2: LIF1 -> GEMM2(HMMA, W2 3-plane) -> LN -> LIF2 + residual -> out
// Grid 128 (2 batches per block, halves on separate named barriers).
// smem: W2 planes 0..196608 | sbf 196608..230400 | params 230400..231936
// ---------------------------------------------------------------------------
#define W2P      65536
#define OFF_SBF  (3*W2P)                   // 196608
#define SBF_BYTES 16896                    // 32 rows x 528 B
#define OFF_PAR  (OFF_SBF + 2*SBF_BYTES)   // 230400
#define F2_SMEM  231936

__global__ __launch_bounds__(512, 1)
void fused2_kernel(const float* __restrict__ x,
                   const float* __restrict__ b2,
                   const float* __restrict__ g2,
                   const float* __restrict__ be2,
                   float* __restrict__ out)
{
    extern __shared__ __align__(16) char smem[];
    const int tid  = threadIdx.x;
    const int lane = tid & 31;

    char*  wsm  = smem;                              // 3 W2 planes
    float* b2s  = (float*)(smem + OFF_PAR);
    float* g2s  = b2s + 128;
    float* be2s = g2s + 128;

    const int half = tid >> 8;
    const int htid = tid & 255;
    const int w8   = (tid >> 5) & 7;                 // warp within half
    const int hbar = 1 + half;                       // named barrier per half
    char*  sbf = smem + OFF_SBF + half * SBF_BYTES;  // [32 t][528 B] bf16
    float* os  = (float*)sbf;                        // alias [32][128] f32

    const int b = blockIdx.x * 2 + half;
    const float* h1base = g_h1 + (size_t)b * (TT * HH);
    const size_t xbase  = (size_t)b * (TT * DD);

    if (tid < 128) { b2s[tid] = b2[tid]; g2s[tid] = g2[tid]; be2s[tid] = be2[tid]; }

    // prefetch chunk 0 (g_h1 is L2-resident: 67 MB < 126 MB L2)
    float pf[32];
    #pragma unroll
    for (int t = 0; t < 32; t++) pf[t] = h1base[t*HH + htid];

    // Stage W2 planes: straight copy (prep kernel already split+swizzled)
    {
        const uint4* src = (const uint4*)g_w2p;   // 12288 uint4
        uint4* dst = (uint4*)wsm;
        #pragma unroll 6
        for (int i = 0; i < 24; i++) dst[tid + i*512] = src[tid + i*512];
    }
    __syncthreads();   // W2 planes + params visible to both halves

    // warp tiling: M=32 t (2 mtiles), N=16 d (w8*16), 5 LDSM : 12 MMA / ks
    const uint32_t wsm_u = smem_to_u32(wsm);
    const uint32_t abase = smem_to_u32(sbf) + (uint32_t)(lane & 15)*528
                         + ((lane >> 4) << 4);
    const int brow0 = w8*16 + (lane & 7) + ((lane >> 4) << 3);
    const int bsel  = (lane >> 3) & 1;

    float v1 = 0.f, v2 = 0.f;

    for (int c = 0; c < 8; c++) {
        // ---- LIF1: spikes as constant bf16 bits ----
        {
            float v = v1;
            #pragma unroll
            for (int t = 0; t < 32; t++) {
                float hm = v + (pf[t] - v) * 0.5f;
                *(uint16_t*)(sbf + t*528 + htid*2) = (hm >= 1.f) ? 0x3F80u : 0u;
                v = (hm >= 1.f) ? 0.f : hm;
            }
            v1 = v;
        }
        BARN(hbar, 256);

        if (c + 1 < 8) {
            const float* hn = h1base + (size_t)(c+1) * 32 * HH;
            #pragma unroll
            for (int t = 0; t < 32; t++) pf[t] = hn[t*HH + htid];
        }

        // ---- GEMM2 ----
        float D[2][2][4];
        #pragma unroll
        for (int mt = 0; mt < 2; mt++)
            #pragma unroll
            for (int nt = 0; nt < 2; nt++) {
                int col = w8*16 + nt*8 + (lane & 3)*2;
                D[mt][nt][0] = b2s[col]; D[mt][nt][1] = b2s[col+1];
                D[mt][nt][2] = b2s[col]; D[mt][nt][3] = b2s[col+1];
            }
        for (int ks = 0; ks < 16; ks++) {
            uint32_t a0[4], a1[4];
            LDSM4(a0, abase + ks*32);
            LDSM4(a1, abase + 16*528 + ks*32);
            uint32_t boff = (uint32_t)brow0*512 +
                            ((((ks << 1) | bsel) ^ (brow0 & 7)) << 4);
            #pragma unroll
            for (int p = 0; p < 3; p++) {
                uint32_t bb[4];
                LDSM4(bb, wsm_u + p*W2P + boff);
                MMA16816(D[0][0], a0, bb[0], bb[1]);
                MMA16816(D[0][1], a0, bb[2], bb[3]);
                MMA16816(D[1][0], a1, bb[0], bb[1]);
                MMA16816(D[1][1], a1, bb[2], bb[3]);
            }
        }
        BARN(hbar, 256);   // reads of sbf done before os (alias) writes

        // ---- store D -> os[32][128] ----
        {
            int r0 = lane >> 2;
            #pragma unroll
            for (int mt = 0; mt < 2; mt++)
                #pragma unroll
                for (int nt = 0; nt < 2; nt++) {
                    int col = w8*16 + nt*8 + (lane & 3)*2;
                    *(float2*)(os + (mt*16 + r0)*128 + col)
                        = make_float2(D[mt][nt][0], D[mt][nt][1]);
                    *(float2*)(os + (mt*16 + r0 + 8)*128 + col)
                        = make_float2(D[mt][nt][2], D[mt][nt][3]);
                }
        }
        BARN(hbar, 256);

        // ---- LayerNorm over D=128 per row (8 warps x 4 rows) ----
        #pragma unroll
        for (int rr = 0; rr < 4; rr++) {
            int row = w8*4 + rr;
            float v[4];
            #pragma unroll
            for (int i = 0; i < 4; i++) v[i] = os[row*128 + lane + 32*i];
            float sum = 0.f, sq = 0.f;
            #pragma unroll
            for (int i = 0; i < 4; i++) { sum += v[i]; sq += v[i]*v[i]; }
            #pragma unroll
            for (int o = 16; o; o >>= 1) {
                sum += __shfl_xor_sync(0xffffffffu, sum, o);
                sq  += __shfl_xor_sync(0xffffffffu, sq,  o);
            }
            float mean = sum * (1.f/128.f);
            float var  = fmaxf(sq * (1.f/128.f) - mean*mean, 0.f) + 1e-5f;
            float inv  = rsqrtf(var);
            inv = inv * (1.5f - 0.5f * var * inv * inv);
            #pragma unroll
            for (int i = 0; i < 4; i++) {
                int dd2 = lane + 32*i;
                os[row*128 + dd2] = (v[i] - mean) * inv * g2s[dd2] + be2s[dd2];
            }
        }
        BARN(hbar, 256);

        // ---- LIF2 + residual ----
        if (htid < 128) {
            const float* xp = x   + xbase + (size_t)c * 32 * DD + htid;
            float*       op = out + xbase + (size_t)c * 32 * DD + htid;
            float v = v2;
            #pragma unroll
            for (int t = 0; t < 32; t++) {
                float hm = v + (os[t*128 + htid] - v) * 0.5f;
                float s  = (hm >= 1.f) ? 1.f : 0.f;
                v = (hm >= 1.f) ? 0.f : hm;
                op[(size_t)t * DD] = xp[(size_t)t * DD] + s;
            }
            v2 = v;
        }
        BARN(hbar, 256);   // before next chunk overwrites sbf/os
    }
}

// ---------------------------------------------------------------------------
extern "C" void kernel_launch(void* const* d_in, const int* in_sizes, int n_in,
                              void* d_out, int out_size)
{
    const float* x   = (const float*)d_in[0];
    const float* W1  = (const float*)d_in[1];
    const float* b1  = (const float*)d_in[2];
    const float* g1  = (const float*)d_in[3];
    const float* be1 = (const float*)d_in[4];
    const float* W2  = (const float*)d_in[5];
    const float* b2  = (const float*)d_in[6];
    const float* g2  = (const float*)d_in[7];
    const float* be2 = (const float*)d_in[8];
    float* out = (float*)d_out;

    (void)in_sizes; (void)n_in; (void)out_size;

    cudaFuncSetAttribute(gemm1_kernel,
                         cudaFuncAttributeMaxDynamicSharedMemorySize, G1_SMEM);
    cudaFuncSetAttribute(fused2_kernel,
                         cudaFuncAttributeMaxDynamicSharedMemorySize, F2_SMEM);

    prep_kernel<<<64, 512>>>(W1, W2);
    gemm1_kernel<<<NROWS/128, 512, G1_SMEM>>>(x, b1, g1, be1);
    fused2_kernel<<<BB/2, 512, F2_SMEM>>>(x, b2, g2, be2, out);
}

// round 17
// speedup vs baseline: 1.1389x; 1.1389x over previous
#include <cuda_runtime.h>
#include <cuda_bf16.h>
#include <cstdint>

// Problem dims (fixed by the dataset)
#define BB 256
#define TT 256
#define DD 128
#define HH 256
#define NROWS (BB*TT)          // 65536

// Scratch: h1 (post-LN, pre-LIF1) [B,T,H]; pre-split swizzled W planes
__device__ __align__(16) float g_h1[(size_t)NROWS * HH];   // 67 MB
__device__ __align__(16) unsigned char g_w1p[3*65536];     // W1 bf16x3 planes
__device__ __align__(16) unsigned char g_w2p[3*65536];     // W2 bf16x3 planes

// ---------------------------------------------------------------------------
// mma.sync / ldmatrix helpers (family-portable; NO tcgen05 — harness PTX
// target is plain sm_103, arch-specific features are rejected by ptxas)
// ---------------------------------------------------------------------------
__device__ __forceinline__ uint32_t smem_to_u32(const void* p) {
    uint32_t a;
    asm("{ .reg .u64 t; cvta.to.shared.u64 t, %1; cvt.u32.u64 %0, t; }"
        : "=r"(a) : "l"(p));
    return a;
}
#define LDSM4(r, addr) \
    asm volatile("ldmatrix.sync.aligned.m8n8.x4.shared.b16 {%0,%1,%2,%3}, [%4];" \
        : "=r"((r)[0]), "=r"((r)[1]), "=r"((r)[2]), "=r"((r)[3]) : "r"(addr))
#define MMA16816(D, a, b0, b1) \
    asm volatile("mma.sync.aligned.m16n8k16.row.col.f32.bf16.bf16.f32 " \
        "{%0,%1,%2,%3}, {%4,%5,%6,%7}, {%8,%9}, {%0,%1,%2,%3};" \
        : "+f"((D)[0]), "+f"((D)[1]), "+f"((D)[2]), "+f"((D)[3]) \
        : "r"((a)[0]), "r"((a)[1]), "r"((a)[2]), "r"((a)[3]), "r"(b0), "r"(b1))
// named barriers: group-scope sync (ids 1-7; 0 is __syncthreads)
#define BARN(id, cnt) asm volatile("bar.sync %0, %1;" :: "r"(id), "r"(cnt) : "memory")

__device__ __forceinline__ uint32_t packbf(__nv_bfloat16 a, __nv_bfloat16 b) {
    return (uint32_t)__bfloat16_as_ushort(a) | ((uint32_t)__bfloat16_as_ushort(b) << 16);
}
// scalar split (prep kernel only): f = h + m + l
__device__ __forceinline__ void split3(float2 f, uint32_t& h, uint32_t& m, uint32_t& l) {
    __nv_bfloat16 hx = __float2bfloat16(f.x); float rx = f.x - __bfloat162float(hx);
    __nv_bfloat16 mx = __float2bfloat16(rx);  rx -= __bfloat162float(mx);
    __nv_bfloat16 lx = __float2bfloat16(rx);
    __nv_bfloat16 hy = __float2bfloat16(f.y); float ry = f.y - __bfloat162float(hy);
    __nv_bfloat16 my = __float2bfloat16(ry);  ry -= __bfloat162float(my);
    __nv_bfloat16 ly = __float2bfloat16(ry);
    h = packbf(hx, hy); m = packbf(mx, my); l = packbf(lx, ly);
}
// packed split (hot path): bf16x2 cvt + shift/mask upconvert; bit-identical
__device__ __forceinline__ void split3p(float2 f, uint32_t& h, uint32_t& m, uint32_t& l) {
    asm("cvt.rn.bf16x2.f32 %0, %1, %2;" : "=r"(h) : "f"(f.y), "f"(f.x));
    float rx = f.x - __uint_as_float(h << 16);
    float ry = f.y - __uint_as_float(h & 0xFFFF0000u);
    asm("cvt.rn.bf16x2.f32 %0, %1, %2;" : "=r"(m) : "f"(ry), "f"(rx));
    float sx = rx - __uint_as_float(m << 16);
    float sy = ry - __uint_as_float(m & 0xFFFF0000u);
    asm("cvt.rn.bf16x2.f32 %0, %1, %2;" : "=r"(l) : "f"(sy), "f"(sx));
}

// ---------------------------------------------------------------------------
// Prep kernel: split W1/W2 into swizzled bf16 planes ONCE
// ---------------------------------------------------------------------------
__global__ __launch_bounds__(512)
void prep_kernel(const float* __restrict__ W1, const float* __restrict__ W2)
{
    int idx = blockIdx.x * 512 + threadIdx.x;     // 0..32767
    if (idx < 16384) {                            // W1: [h=256][k=128]
        int h = idx >> 6, k = (idx & 63) * 2;
        float2 w = *(const float2*)(W1 + h*128 + k);
        uint32_t ph, pm, pl;
        split3(w, ph, pm, pl);
        uint32_t off = (uint32_t)h*256 + ((((uint32_t)k >> 3) ^ (h & 7)) << 4)
                     + ((k & 7) << 1);
        *(uint32_t*)(g_w1p + off)           = ph;
        *(uint32_t*)(g_w1p + 65536 + off)   = pm;
        *(uint32_t*)(g_w1p + 2*65536 + off) = pl;
    } else {                                      // W2: [d=128][k=256]
        int j = idx - 16384;
        int dd = j >> 7, k = (j & 127) * 2;
        float2 w = *(const float2*)(W2 + dd*256 + k);
        uint32_t ph, pm, pl;
        split3(w, ph, pm, pl);
        uint32_t off = (uint32_t)dd*512 + ((((uint32_t)k >> 3) ^ (dd & 7)) << 4)
                     + ((k & 7) << 1);
        *(uint32_t*)(g_w2p + off)           = ph;
        *(uint32_t*)(g_w2p + 65536 + off)   = pm;
        *(uint32_t*)(g_w2p + 2*65536 + off) = pl;
    }
}

// ---------------------------------------------------------------------------
// smem layout (R15 proven)
// Phase 1: params 0..3071 | red 3072..7168 | W1 planes 8192..204800
// Phase 2: W2 planes 0..196608 | sbf 196608..230400 | params 230400..231936
// ---------------------------------------------------------------------------
#define OFF_RED  3072
#define OFF_W    8192
#define W1P      65536

#define W2P      65536
#define OFF_SBF  (3*W2P)                   // 196608
#define SBF_BYTES 16896                    // 32 rows x 528 B
#define OFF_PAR  (OFF_SBF + 2*SBF_BYTES)   // 230400
#define SMEM_BYTES 231936

__global__ __launch_bounds__(512, 1)
void spiking_block_kernel(const float* __restrict__ x,
                          const float* __restrict__ b1,
                          const float* __restrict__ g1,
                          const float* __restrict__ be1,
                          const float* __restrict__ b2,
                          const float* __restrict__ g2,
                          const float* __restrict__ be2,
                          float* __restrict__ out)
{
    extern __shared__ __align__(16) char smem[];
    const int tid  = threadIdx.x;
    const int lane = tid & 31;
    const int wid  = tid >> 5;

    // ======================= PHASE 1: GEMM1 + LN -> g_h1 ====================
    // A fragments in registers from gmem; W1 planes read-only in smem;
    // ZERO main-loop barriers. MMA bundle is TERM-OUTER: each accumulator's
    // RAW chain spaced by 3 independent MMAs (per-accumulator order unchanged
    // -> bit-identical accumulation).
    {
        float* b1s  = (float*)smem;
        float* g1s  = b1s + 256;
        float* be1s = g1s + 256;
        float* red  = (float*)(smem + OFF_RED);   // [128 rows][8] per-group disjoint
        char*  wsm  = smem + OFF_W;

        if (tid < 256) { b1s[tid] = b1[tid]; g1s[tid] = g1[tid]; be1s[tid] = be1[tid]; }

        // Stage W1 planes: straight copy (prep kernel already split+swizzled)
        {
            const uint4* src = (const uint4*)g_w1p;   // 12288 uint4
            uint4* dst = (uint4*)wsm;
            #pragma unroll 6
            for (int i = 0; i < 24; i++) dst[tid + i*512] = src[tid + i*512];
        }

        const int wm = wid >> 2, wn = wid & 3;
        const int gbar = 4 + wm;               // named barrier id for this group
        const int brow = wn*64 + (lane & 7) + ((lane >> 4) << 3);
        const int bsel = (lane >> 3) & 1;
        const uint32_t wsm_u = smem_to_u32(wsm);
        __syncthreads();   // W1 planes + params visible; only sync in phase 1

        for (int tt = 0; tt < 4; tt++) {
            const int rowBase = (blockIdx.x*4 + tt) * 128;
            const float* xg = x + (size_t)(rowBase + wm*32) * DD;

            float d[2][8][4];
            #pragma unroll
            for (int mt = 0; mt < 2; mt++)
                #pragma unroll
                for (int nt = 0; nt < 8; nt++)
                    #pragma unroll
                    for (int i = 0; i < 4; i++) d[mt][nt][i] = 0.f;

            // prefetch ks=0 fragments: 4 float2 per mtile
            float2 pf[2][4];
            #pragma unroll
            for (int mt = 0; mt < 2; mt++) {
                const float* xr = xg + (mt*16 + (lane >> 2))*DD + (lane & 3)*2;
                pf[mt][0] = *(const float2*)(xr);
                pf[mt][1] = *(const float2*)(xr + 8*DD);
                pf[mt][2] = *(const float2*)(xr + 8);
                pf[mt][3] = *(const float2*)(xr + 8*DD + 8);
            }

            for (int ks = 0; ks < 8; ks++) {
                // build A fragments in registers (bit-identical planes)
                uint32_t ah[2][4], am[2][4], al[2][4];
                #pragma unroll
                for (int mt = 0; mt < 2; mt++)
                    #pragma unroll
                    for (int i = 0; i < 4; i++)
                        split3p(pf[mt][i], ah[mt][i], am[mt][i], al[mt][i]);

                // prefetch ks+1 (hidden behind MMA burst)
                if (ks < 7) {
                    #pragma unroll
                    for (int mt = 0; mt < 2; mt++) {
                        const float* xr = xg + (mt*16 + (lane >> 2))*DD
                                        + (ks+1)*16 + (lane & 3)*2;
                        pf[mt][0] = *(const float2*)(xr);
                        pf[mt][1] = *(const float2*)(xr + 8*DD);
                        pf[mt][2] = *(const float2*)(xr + 8);
                        pf[mt][3] = *(const float2*)(xr + 8*DD + 8);
                    }
                }

                #pragma unroll
                for (int np = 0; np < 4; np++) {
                    int row = brow + np*16;
                    uint32_t boff = (uint32_t)row*256 +
                                    ((((ks << 1) | bsel) ^ (row & 7)) << 4);
                    uint32_t bh[4], bm[4], bl[4];
                    LDSM4(bh, wsm_u + boff);
                    LDSM4(bm, wsm_u + W1P + boff);
                    LDSM4(bl, wsm_u + 2*W1P + boff);
                    // term-outer: all 4 accumulators per term before next term
                    #pragma unroll
                    for (int mt = 0; mt < 2; mt++)
                        #pragma unroll
                        for (int ns = 0; ns < 2; ns++)
                            MMA16816(d[mt][np*2 + ns], ah[mt], bh[ns*2], bh[ns*2+1]); // hh
                    #pragma unroll
                    for (int mt = 0; mt < 2; mt++)
                        #pragma unroll
                        for (int ns = 0; ns < 2; ns++)
                            MMA16816(d[mt][np*2 + ns], ah[mt], bm[ns*2], bm[ns*2+1]); // hm
                    #pragma unroll
                    for (int mt = 0; mt < 2; mt++)
                        #pragma unroll
                        for (int ns = 0; ns < 2; ns++)
                            MMA16816(d[mt][np*2 + ns], am[mt], bh[ns*2], bh[ns*2+1]); // mh
                    #pragma unroll
                    for (int mt = 0; mt < 2; mt++)
                        #pragma unroll
                        for (int ns = 0; ns < 2; ns++)
                            MMA16816(d[mt][np*2 + ns], am[mt], bm[ns*2], bm[ns*2+1]); // mm
                    #pragma unroll
                    for (int mt = 0; mt < 2; mt++)
                        #pragma unroll
                        for (int ns = 0; ns < 2; ns++)
                            MMA16816(d[mt][np*2 + ns], ah[mt], bl[ns*2], bl[ns*2+1]); // hl
                    #pragma unroll
                    for (int mt = 0; mt < 2; mt++)
                        #pragma unroll
                        for (int ns = 0; ns < 2; ns++)
                            MMA16816(d[mt][np*2 + ns], al[mt], bh[ns*2], bh[ns*2+1]); // lh
                }
            }

            // ---- epilogue (group-local): bias + LN + store ----
            float psum[2][2] = {{0.f,0.f},{0.f,0.f}}, psq[2][2] = {{0.f,0.f},{0.f,0.f}};
            #pragma unroll
            for (int mt = 0; mt < 2; mt++)
                #pragma unroll
                for (int nt = 0; nt < 8; nt++) {
                    int col = wn*64 + nt*8 + (lane & 3)*2;
                    float bx = b1s[col], by = b1s[col+1];
                    float* D = d[mt][nt];
                    D[0] += bx; D[1] += by; D[2] += bx; D[3] += by;
                    psum[mt][0] += D[0] + D[1]; psq[mt][0] += D[0]*D[0] + D[1]*D[1];
                    psum[mt][1] += D[2] + D[3]; psq[mt][1] += D[2]*D[2] + D[3]*D[3];
                }
            #pragma unroll
            for (int mt = 0; mt < 2; mt++)
                #pragma unroll
                for (int rh = 0; rh < 2; rh++) {
                    #pragma unroll
                    for (int o = 1; o <= 2; o <<= 1) {
                        psum[mt][rh] += __shfl_xor_sync(0xffffffffu, psum[mt][rh], o);
                        psq[mt][rh]  += __shfl_xor_sync(0xffffffffu, psq[mt][rh],  o);
                    }
                    if ((lane & 3) == 0) {
                        int r = wm*32 + mt*16 + rh*8 + (lane >> 2);
                        red[r*8 + wn*2 + 0] = psum[mt][rh];
                        red[r*8 + wn*2 + 1] = psq[mt][rh];
                    }
                }
            BARN(gbar, 128);   // red rows for this group complete

            #pragma unroll
            for (int mt = 0; mt < 2; mt++) {
                int r0 = wm*32 + mt*16 + (lane >> 2);
                int r1 = r0 + 8;
                float s0 = red[r0*8+0] + red[r0*8+2] + red[r0*8+4] + red[r0*8+6];
                float q0 = red[r0*8+1] + red[r0*8+3] + red[r0*8+5] + red[r0*8+7];
                float mean0 = s0 * (1.f/256.f);
                float var0  = fmaxf(q0 * (1.f/256.f) - mean0*mean0, 0.f) + 1e-5f;
                float inv0  = rsqrtf(var0);
                inv0 = inv0 * (1.5f - 0.5f * var0 * inv0 * inv0);  // fp32-exact rsqrt
                float s1 = red[r1*8+0] + red[r1*8+2] + red[r1*8+4] + red[r1*8+6];
                float q1 = red[r1*8+1] + red[r1*8+3] + red[r1*8+5] + red[r1*8+7];
                float mean1 = s1 * (1.f/256.f);
                float var1  = fmaxf(q1 * (1.f/256.f) - mean1*mean1, 0.f) + 1e-5f;
                float inv1  = rsqrtf(var1);
                inv1 = inv1 * (1.5f - 0.5f * var1 * inv1 * inv1);
                float* o0 = g_h1 + (size_t)(rowBase + r0) * HH;
                float* o1 = o0 + 8*HH;
                #pragma unroll
                for (int nt = 0; nt < 8; nt++) {
                    int col = wn*64 + nt*8 + (lane & 3)*2;
                    float gx = g1s[col], gy = g1s[col+1];
                    float ex = be1s[col], ey = be1s[col+1];
                    float* D = d[mt][nt];
                    float2 w0, w1;
                    w0.x = (D[0] - mean0) * inv0 * gx + ex;
                    w0.y = (D[1] - mean0) * inv0 * gy + ey;
                    w1.x = (D[2] - mean1) * inv1 * gx + ex;
                    w1.y = (D[3] - mean1) * inv1 * gy + ey;
                    *(float2*)(o0 + col) = w0;
                    *(float2*)(o1 + col) = w1;
                }
            }
            BARN(gbar, 128);   // before next tile reuses red (group-local)
        }
    }
    __syncthreads();   // phase boundary: all groups done reading W1 planes

    // ====== PHASE 2: LIF1 -> GEMM2(HMMA, W2 3-plane) -> LN -> LIF2 + res ====
    // (identical to R11/R14/R15's proven flow)
    {
        char*  wsm  = smem;                              // 3 W2 planes
        float* b2s  = (float*)(smem + OFF_PAR);
        float* g2s  = b2s + 128;
        float* be2s = g2s + 128;

        const int half = tid >> 8;
        const int htid = tid & 255;
        const int w8   = (tid >> 5) & 7;                 // warp within half
        const int hbar = 1 + half;                       // named barrier per half
        char*  sbf = smem + OFF_SBF + half * SBF_BYTES;  // [32 t][528 B] bf16
        float* os  = (float*)sbf;                        // alias [32][128] f32

        const int b = blockIdx.x * 2 + half;
        const float* h1base = g_h1 + (size_t)b * (TT * HH);
        const size_t xbase  = (size_t)b * (TT * DD);

        if (tid < 128) { b2s[tid] = b2[tid]; g2s[tid] = g2[tid]; be2s[tid] = be2[tid]; }

        // prefetch chunk 0 (L2-hot: written by this block in phase 1)
        float pf[32];
        #pragma unroll
        for (int t = 0; t < 32; t++) pf[t] = h1base[t*HH + htid];

        // Stage W2 planes: straight copy (prep kernel already split+swizzled)
        {
            const uint4* src = (const uint4*)g_w2p;   // 12288 uint4
            uint4* dst = (uint4*)wsm;
            #pragma unroll 6
            for (int i = 0; i < 24; i++) dst[tid + i*512] = src[tid + i*512];
        }
        __syncthreads();   // W2 planes + params visible to both halves

        // warp tiling: M=32 t (2 mtiles), N=16 d (w8*16), 5 LDSM : 12 MMA / ks
        const uint32_t wsm_u = smem_to_u32(wsm);
        const uint32_t abase = smem_to_u32(sbf) + (uint32_t)(lane & 15)*528
                             + ((lane >> 4) << 4);
        const int brow0 = w8*16 + (lane & 7) + ((lane >> 4) << 3);
        const int bsel  = (lane >> 3) & 1;

        float v1 = 0.f, v2 = 0.f;

        for (int c = 0; c < 8; c++) {
            // ---- LIF1: spikes as constant bf16 bits ----
            {
                float v = v1;
                #pragma unroll
                for (int t = 0; t < 32; t++) {
                    float hm = v + (pf[t] - v) * 0.5f;
                    *(uint16_t*)(sbf + t*528 + htid*2) = (hm >= 1.f) ? 0x3F80u : 0u;
                    v = (hm >= 1.f) ? 0.f : hm;
                }
                v1 = v;
            }
            BARN(hbar, 256);

            if (c + 1 < 8) {
                const float* hn = h1base + (size_t)(c+1) * 32 * HH;
                #pragma unroll
                for (int t = 0; t < 32; t++) pf[t] = hn[t*HH + htid];
            }

            // ---- GEMM2 ----
            float D[2][2][4];
            #pragma unroll
            for (int mt = 0; mt < 2; mt++)
                #pragma unroll
                for (int nt = 0; nt < 2; nt++) {
                    int col = w8*16 + nt*8 + (lane & 3)*2;
                    D[mt][nt][0] = b2s[col]; D[mt][nt][1] = b2s[col+1];
                    D[mt][nt][2] = b2s[col]; D[mt][nt][3] = b2s[col+1];
                }
            for (int ks = 0; ks < 16; ks++) {
                uint32_t a0[4], a1[4];
                LDSM4(a0, abase + ks*32);
                LDSM4(a1, abase + 16*528 + ks*32);
                uint32_t boff = (uint32_t)brow0*512 +
                                ((((ks << 1) | bsel) ^ (brow0 & 7)) << 4);
                #pragma unroll
                for (int p = 0; p < 3; p++) {
                    uint32_t bb[4];
                    LDSM4(bb, wsm_u + p*W2P + boff);
                    MMA16816(D[0][0], a0, bb[0], bb[1]);
                    MMA16816(D[0][1], a0, bb[2], bb[3]);
                    MMA16816(D[1][0], a1, bb[0], bb[1]);
                    MMA16816(D[1][1], a1, bb[2], bb[3]);
                }
            }
            BARN(hbar, 256);   // reads of sbf done before os (alias) writes

            // ---- store D -> os[32][128] ----
            {
                int r0 = lane >> 2;
                #pragma unroll
                for (int mt = 0; mt < 2; mt++)
                    #pragma unroll
                    for (int nt = 0; nt < 2; nt++) {
                        int col = w8*16 + nt*8 + (lane & 3)*2;
                        *(float2*)(os + (mt*16 + r0)*128 + col)
                            = make_float2(D[mt][nt][0], D[mt][nt][1]);
                        *(float2*)(os + (mt*16 + r0 + 8)*128 + col)
                            = make_float2(D[mt][nt][2], D[mt][nt][3]);
                    }
            }
            BARN(hbar, 256);

            // ---- LayerNorm over D=128 per row (8 warps x 4 rows) ----
            #pragma unroll
            for (int rr = 0; rr < 4; rr++) {
                int row = w8*4 + rr;
                float v[4];
                #pragma unroll
                for (int i = 0; i < 4; i++) v[i] = os[row*128 + lane + 32*i];
                float sum = 0.f, sq = 0.f;
                #pragma unroll
                for (int i = 0; i < 4; i++) { sum += v[i]; sq += v[i]*v[i]; }
                #pragma unroll
                for (int o = 16; o; o >>= 1) {
                    sum += __shfl_xor_sync(0xffffffffu, sum, o);
                    sq  += __shfl_xor_sync(0xffffffffu, sq,  o);
                }
                float mean = sum * (1.f/128.f);
                float var  = fmaxf(sq * (1.f/128.f) - mean*mean, 0.f) + 1e-5f;
                float inv  = rsqrtf(var);
                inv = inv * (1.5f - 0.5f * var * inv * inv);
                #pragma unroll
                for (int i = 0; i < 4; i++) {
                    int dd2 = lane + 32*i;
                    os[row*128 + dd2] = (v[i] - mean) * inv * g2s[dd2] + be2s[dd2];
                }
            }
            BARN(hbar, 256);

            // ---- LIF2 + residual ----
            if (htid < 128) {
                const float* xp = x   + xbase + (size_t)c * 32 * DD + htid;
                float*       op = out + xbase + (size_t)c * 32 * DD + htid;
                float v = v2;
                #pragma unroll
                for (int t = 0; t < 32; t++) {
                    float hm = v + (os[t*128 + htid] - v) * 0.5f;
                    float s  = (hm >= 1.f) ? 1.f : 0.f;
                    v = (hm >= 1.f) ? 0.f : hm;
                    op[(size_t)t * DD] = xp[(size_t)t * DD] + s;
                }
                v2 = v;
            }
            BARN(hbar, 256);   // before next chunk overwrites sbf/os
        }
    }
}

// ---------------------------------------------------------------------------
extern "C" void kernel_launch(void* const* d_in, const int* in_sizes, int n_in,
                              void* d_out, int out_size)
{
    const float* x   = (const float*)d_in[0];
    const float* W1  = (const float*)d_in[1];
    const float* b1  = (const float*)d_in[2];
    const float* g1  = (const float*)d_in[3];
    const float* be1 = (const float*)d_in[4];
    const float* W2  = (const float*)d_in[5];
    const float* b2  = (const float*)d_in[6];
    const float* g2  = (const float*)d_in[7];
    const float* be2 = (const float*)d_in[8];
    float* out = (float*)d_out;

    (void)in_sizes; (void)n_in; (void)out_size;

    cudaFuncSetAttribute(spiking_block_kernel,
                         cudaFuncAttributeMaxDynamicSharedMemorySize, SMEM_BYTES);

    prep_kernel<<<64, 512>>>(W1, W2);
    spiking_block_kernel<<<BB/2, 512, SMEM_BYTES>>>(x, b1, g1, be1,
                                                    b2, g2, be2, out);
}